// round 7
// baseline (speedup 1.0000x reference)
#include <cuda_runtime.h>
#include <cstdint>

// Sinkhorn as diagonal scaling, single persistent cluster kernel.
// out = (s+eps)*u9[r]*v8[c] on the valid block, 0 outside.
// v_{2k} = 1/(M^T u_{2k-1}), u_{2k+1} = 1/(M v_{2k}), u0 = 1 on valid rows.
//
// R7: keep R5's traffic structure (32 clusters x 8 CTAs, 2 batches each ->
// 484MB DRAM, verified), but break the latency-bound row loop into two
// streaming phases over 4-row groups: phase1 computes 4 row-dots with
// independent chains (deep MLP, pipelined shuffles), phase2 re-streams the
// rows (L1/L2 hot) to accumulate column sums. No per-row load->reduce->use
// serialization remains.

#define NB     64
#define NN     1024
#define EPS    1e-4f
#define CSZ    8       // CTAs per cluster
#define NCLUS  32      // concurrent clusters (batches in flight)
#define RPC    128     // rows per CTA
#define RPW    16      // rows per warp (8 warps)
#define GRPR   4       // rows per group (phase granularity)

__device__ __forceinline__ uint32_t smem_u32(const void* p) {
    uint32_t a;
    asm("{ .reg .u64 t; cvta.to.shared.u64 t, %1; cvt.u32.u64 %0, t; }"
        : "=r"(a) : "l"(p));
    return a;
}
__device__ __forceinline__ uint32_t mapa_u32(uint32_t local, uint32_t rank) {
    uint32_t r;
    asm("mapa.shared::cluster.u32 %0, %1, %2;" : "=r"(r) : "r"(local), "r"(rank));
    return r;
}
__device__ __forceinline__ float ld_cluster(uint32_t a) {
    float v;
    asm volatile("ld.shared::cluster.f32 %0, [%1];" : "=f"(v) : "r"(a));
    return v;
}
__device__ __forceinline__ void st_cluster(uint32_t a, float v) {
    asm volatile("st.shared::cluster.f32 [%0], %1;" :: "r"(a), "f"(v));
}
// arrive (no .relaxed) = release, wait = acquire.
#define CLUSTER_SYNC() do {                                        \
    asm volatile("barrier.cluster.arrive.aligned;" ::: "memory");  \
    asm volatile("barrier.cluster.wait.aligned;"   ::: "memory");  \
} while (0)

__global__ void __cluster_dims__(CSZ, 1, 1) __launch_bounds__(256, 2)
sinkhorn_kernel(const float* __restrict__ s,
                float*       __restrict__ out,
                const int*   __restrict__ nrows,
                const int*   __restrict__ ncols)
{
    __shared__ float  v_s[NN];          // current column scales (0 beyond nc)
    __shared__ float  acc_s[NN];        // this CTA's partial column sums
    __shared__ float4 stage[8][256];    // per-warp accumulator staging

    const int rank = blockIdx.x;        // cluster rank 0..7
    const int clus = blockIdx.y;        // cluster id 0..31
    const int warp = threadIdx.x >> 5;
    const int lane = threadIdx.x & 31;

    const uint32_t a_acc = smem_u32(acc_s);
    const uint32_t a_v   = smem_u32(v_s);

    for (int b = clus; b < NB; b += NCLUS) {
        const int nr = nrows[b];
        const int nc = ncols[b];
        const int mylim = nc - 4 * lane;   // chunk f needed iff 128*f < mylim

        const float4* sb = (const float4*)(s + (size_t)b * NN * NN);
        const int rbase  = rank * RPC + warp * RPW;

        // ---- 5 accumulation passes: pass0 (u=1) -> v0; 1..4 -> v2,v4,v6,v8
        for (int pass = 0; pass < 5; pass++) {
            const bool FIRST = (pass == 0);

            float4 v4[8];
            if (!FIRST) {
                const float4* vv = (const float4*)v_s;
#pragma unroll
                for (int f = 0; f < 8; f++)
                    v4[f] = (128 * f < mylim) ? vv[f * 32 + lane]
                                              : make_float4(0.f, 0.f, 0.f, 0.f);
            }

            float4 acc[8];
#pragma unroll
            for (int f = 0; f < 8; f++) acc[f] = make_float4(0.f, 0.f, 0.f, 0.f);

            for (int g = 0; g < RPW / GRPR; g++) {
                const int r0  = rbase + g * GRPR;
                const int cnt = min(GRPR, nr - r0);
                if (cnt <= 0) break;                  // warp-uniform

                float u[GRPR];
                if (FIRST) {
#pragma unroll
                    for (int i = 0; i < GRPR; i++) u[i] = 1.0f;
                } else {
                    // phase 1: 4 independent row-dot chains (streaming)
                    float4 dv[GRPR];
#pragma unroll
                    for (int i = 0; i < GRPR; i++)
                        dv[i] = make_float4(0.f, 0.f, 0.f, 0.f);
#pragma unroll
                    for (int i = 0; i < GRPR; i++) {
                        if (i >= cnt) break;
                        const float4* rp = sb + (size_t)(r0 + i) * 256;
#pragma unroll
                        for (int f = 0; f < 8; f++)
                            if (128 * f < mylim) {
                                float4 x = rp[f * 32 + lane];
                                dv[i].x += (x.x + EPS) * v4[f].x;
                                dv[i].y += (x.y + EPS) * v4[f].y;
                                dv[i].z += (x.z + EPS) * v4[f].z;
                                dv[i].w += (x.w + EPS) * v4[f].w;
                            }
                    }
                    float d[GRPR];
#pragma unroll
                    for (int i = 0; i < GRPR; i++)
                        d[i] = (dv[i].x + dv[i].y) + (dv[i].z + dv[i].w);
                    // 4 independent shuffle-reduce chains (pipelined)
#pragma unroll
                    for (int o = 16; o; o >>= 1) {
#pragma unroll
                        for (int i = 0; i < GRPR; i++)
                            d[i] += __shfl_xor_sync(0xffffffffu, d[i], o);
                    }
#pragma unroll
                    for (int i = 0; i < GRPR; i++) u[i] = 1.0f / d[i];
                }

                // phase 2: re-stream rows (L1/L2 hot), accumulate columns
#pragma unroll
                for (int i = 0; i < GRPR; i++) {
                    if (i >= cnt) break;
                    const float4* rp = sb + (size_t)(r0 + i) * 256;
                    const float ui = u[i];
#pragma unroll
                    for (int f = 0; f < 8; f++)
                        if (128 * f < mylim) {
                            float4 x = rp[f * 32 + lane];
                            acc[f].x += (x.x + EPS) * ui;
                            acc[f].y += (x.y + EPS) * ui;
                            acc[f].z += (x.z + EPS) * ui;
                            acc[f].w += (x.w + EPS) * ui;
                        }
                }
            }

            // CTA-level reduction of warp partials into acc_s
#pragma unroll
            for (int f = 0; f < 8; f++) stage[warp][f * 32 + lane] = acc[f];
            __syncthreads();
            {
                const int j = threadIdx.x;             // owns cols 4j..4j+3
                float4 t = stage[0][j];
#pragma unroll
                for (int w = 1; w < 8; w++) {
                    float4 a = stage[w][j];
                    t.x += a.x; t.y += a.y; t.z += a.z; t.w += a.w;
                }
                ((float4*)acc_s)[j] = t;
            }

            // Cross-CTA column reduction + v update (rank owns 128 cols)
            CLUSTER_SYNC();
            if (threadIdx.x < RPC) {
                const int col = rank * RPC + threadIdx.x;
                float sum = 0.0f;
#pragma unroll
                for (int r = 0; r < CSZ; r++)
                    sum += ld_cluster(mapa_u32(a_acc + 4u * col, r));
                const float vn = (col < nc) ? (1.0f / sum) : 0.0f;
#pragma unroll
                for (int r = 0; r < CSZ; r++)
                    st_cluster(mapa_u32(a_v + 4u * col, r), vn);
            }
            CLUSTER_SYNC();
            __syncthreads();   // acc_s/stage reuse next pass
        }

        // ---- final pass: u9 = 1/(M v8), write out = (s+eps)*u9*v8
        {
            float4 v4[8];
            const float4* vv = (const float4*)v_s;
#pragma unroll
            for (int f = 0; f < 8; f++)
                v4[f] = (128 * f < mylim) ? vv[f * 32 + lane]
                                          : make_float4(0.f, 0.f, 0.f, 0.f);

            float4* ob = (float4*)(out + (size_t)b * NN * NN);
            const float4 z4 = make_float4(0.f, 0.f, 0.f, 0.f);

            for (int g = 0; g < RPW / GRPR; g++) {
                const int r0  = rbase + g * GRPR;
                const int cnt = min(GRPR, max(0, nr - r0));   // valid rows here

                // phase 1: dots for valid rows (streaming)
                float4 dv[GRPR];
#pragma unroll
                for (int i = 0; i < GRPR; i++)
                    dv[i] = make_float4(0.f, 0.f, 0.f, 0.f);
#pragma unroll
                for (int i = 0; i < GRPR; i++) {
                    if (i >= cnt) break;
                    const float4* rp = sb + (size_t)(r0 + i) * 256;
#pragma unroll
                    for (int f = 0; f < 8; f++)
                        if (128 * f < mylim) {
                            float4 x = rp[f * 32 + lane];
                            dv[i].x += (x.x + EPS) * v4[f].x;
                            dv[i].y += (x.y + EPS) * v4[f].y;
                            dv[i].z += (x.z + EPS) * v4[f].z;
                            dv[i].w += (x.w + EPS) * v4[f].w;
                        }
                }
                float d[GRPR];
#pragma unroll
                for (int i = 0; i < GRPR; i++)
                    d[i] = (dv[i].x + dv[i].y) + (dv[i].z + dv[i].w);
#pragma unroll
                for (int o = 16; o; o >>= 1) {
#pragma unroll
                    for (int i = 0; i < GRPR; i++)
                        d[i] += __shfl_xor_sync(0xffffffffu, d[i], o);
                }
                float u[GRPR];
#pragma unroll
                for (int i = 0; i < GRPR; i++) u[i] = 1.0f / d[i];

                // phase 2: write all GRPR rows (zeros for invalid)
#pragma unroll
                for (int i = 0; i < GRPR; i++) {
                    float4* op = ob + (size_t)(r0 + i) * 256;
                    if (i >= cnt) {                    // invalid row: zeros
#pragma unroll
                        for (int f = 0; f < 8; f++)
                            __stcs(&op[f * 32 + lane], z4);
                        continue;
                    }
                    const float4* rp = sb + (size_t)(r0 + i) * 256;
                    const float ui = u[i];
#pragma unroll
                    for (int f = 0; f < 8; f++) {
                        if (128 * f < mylim) {
                            float4 x = rp[f * 32 + lane];
                            float4 o;
                            o.x = (x.x + EPS) * ui * v4[f].x;
                            o.y = (x.y + EPS) * ui * v4[f].y;
                            o.z = (x.z + EPS) * ui * v4[f].z;
                            o.w = (x.w + EPS) * ui * v4[f].w;
                            __stcs(&op[f * 32 + lane], o);  // v==0 past nc -> 0
                        } else {
                            __stcs(&op[f * 32 + lane], z4);
                        }
                    }
                }
            }
        }
        // Next batch's first post-write cluster barrier orders peer v_s/acc_s
        // writes after every rank finished reading them (symmetric arrive).
    }
}

extern "C" void kernel_launch(void* const* d_in, const int* in_sizes, int n_in,
                              void* d_out, int out_size)
{
    const float* s = (const float*)d_in[0];
    const int *nrows, *ncols;
    if (n_in >= 5) {          // order: s, n1, n2, nrows, ncols
        nrows = (const int*)d_in[3];
        ncols = (const int*)d_in[4];
    } else {                  // fallback: s, nrows, ncols
        nrows = (const int*)d_in[1];
        ncols = (const int*)d_in[2];
    }
    float* out = (float*)d_out;

    sinkhorn_kernel<<<dim3(CSZ, NCLUS), 256>>>(s, out, nrows, ncols);
}

// round 10
// speedup vs baseline: 1.0700x; 1.0700x over previous
#include <cuda_runtime.h>
#include <cstdint>

// Sinkhorn as diagonal scaling, single persistent cluster kernel.
// out = (s+eps)*u9[r]*v8[c] on the valid block, 0 outside.
// v_{2k} = 1/(M^T u_{2k-1}), u_{2k+1} = 1/(M v_{2k}), u0 = 1 on valid rows.
//
// R8: same traffic structure as R5 (32 clusters x 8 CTAs, 2 sequential
// batches -> 484MB DRAM verified), but 512-thread CTAs with warp = HALF-row
// (512 cols) so the kernel fits in 64 regs and 2 CTAs/SM co-reside:
// avg warps/SM 14 -> 28. Half-row dots are combined via d_s[2][128] in smem.

#define NB     64
#define NN     1024
#define EPS    1e-4f
#define CSZ    8       // CTAs per cluster
#define NCLUS  32      // concurrent clusters (batches in flight)
#define RPC    128     // rows per CTA
#define HRW    16      // half-rows per warp (16 warps: 8 per column half)
#define GR     4       // rows per group (phase granularity)

__device__ __forceinline__ uint32_t smem_u32(const void* p) {
    uint32_t a;
    asm("{ .reg .u64 t; cvta.to.shared.u64 t, %1; cvt.u32.u64 %0, t; }"
        : "=r"(a) : "l"(p));
    return a;
}
__device__ __forceinline__ uint32_t mapa_u32(uint32_t local, uint32_t rank) {
    uint32_t r;
    asm("mapa.shared::cluster.u32 %0, %1, %2;" : "=r"(r) : "r"(local), "r"(rank));
    return r;
}
__device__ __forceinline__ float ld_cluster(uint32_t a) {
    float v;
    asm volatile("ld.shared::cluster.f32 %0, [%1];" : "=f"(v) : "r"(a));
    return v;
}
__device__ __forceinline__ void st_cluster(uint32_t a, float v) {
    asm volatile("st.shared::cluster.f32 [%0], %1;" :: "r"(a), "f"(v));
}
// arrive (no .relaxed) = release, wait = acquire.
#define CLUSTER_SYNC() do {                                        \
    asm volatile("barrier.cluster.arrive.aligned;" ::: "memory");  \
    asm volatile("barrier.cluster.wait.aligned;"   ::: "memory");  \
} while (0)

__global__ void __cluster_dims__(CSZ, 1, 1) __launch_bounds__(512, 2)
sinkhorn_kernel(const float* __restrict__ s,
                float*       __restrict__ out,
                const int*   __restrict__ nrows,
                const int*   __restrict__ ncols)
{
    __shared__ float  v_s[NN];            // current column scales (0 beyond nc)
    __shared__ float  acc_s[NN];          // this CTA's partial column sums
    __shared__ float  d_s[2][RPC];        // half-row dot results
    __shared__ float4 stage[16][128];     // per-warp accumulator staging (32KB)

    const int rank = blockIdx.x;          // cluster rank 0..7
    const int clus = blockIdx.y;          // cluster id 0..31
    const int warp = threadIdx.x >> 5;
    const int lane = threadIdx.x & 31;
    const int half = warp >> 3;           // column half 0/1
    const int wrow = (warp & 7) * HRW;    // first local row of this warp
    const int cbase = half * 128 + lane;  // float4 index within row (+f*32)

    const uint32_t a_acc = smem_u32(acc_s);
    const uint32_t a_v   = smem_u32(v_s);

    for (int b = clus; b < NB; b += NCLUS) {
        const int nr = nrows[b];
        const int nc = ncols[b];
        // chunk f (cols half*512 + f*128 + 4*lane ..+3) needed iff 128*f < mylim
        const int mylim = nc - half * 512 - 4 * lane;

        const float4* sb = (const float4*)(s + (size_t)b * NN * NN);
        const int rg = rank * RPC + wrow;         // first global row of warp

        // ---- 5 accumulation passes: pass0 (u=1) -> v0; 1..4 -> v2,v4,v6,v8
        for (int pass = 0; pass < 5; pass++) {
            const bool FIRST = (pass == 0);

            // phase 1: half-row dots -> d_s  (skipped when u==1)
            if (!FIRST) {
                float4 v4[4];
                const float4* vv = (const float4*)v_s;
#pragma unroll
                for (int f = 0; f < 4; f++)
                    v4[f] = (128 * f < mylim) ? vv[cbase + f * 32]
                                              : make_float4(0.f, 0.f, 0.f, 0.f);
                for (int g = 0; g < HRW / GR; g++) {
                    const int r0  = rg + g * GR;
                    const int cnt = min(GR, nr - r0);
                    if (cnt <= 0) break;                 // warp-uniform
                    float4 dv[GR];
#pragma unroll
                    for (int i = 0; i < GR; i++)
                        dv[i] = make_float4(0.f, 0.f, 0.f, 0.f);
#pragma unroll
                    for (int i = 0; i < GR; i++) {
                        if (i >= cnt) break;
                        const float4* rp = sb + (size_t)(r0 + i) * 256;
#pragma unroll
                        for (int f = 0; f < 4; f++)
                            if (128 * f < mylim) {
                                float4 x = rp[cbase + f * 32];
                                dv[i].x += (x.x + EPS) * v4[f].x;
                                dv[i].y += (x.y + EPS) * v4[f].y;
                                dv[i].z += (x.z + EPS) * v4[f].z;
                                dv[i].w += (x.w + EPS) * v4[f].w;
                            }
                    }
                    float d[GR];
#pragma unroll
                    for (int i = 0; i < GR; i++)
                        d[i] = (dv[i].x + dv[i].y) + (dv[i].z + dv[i].w);
#pragma unroll
                    for (int o = 16; o; o >>= 1) {
#pragma unroll
                        for (int i = 0; i < GR; i++)
                            d[i] += __shfl_xor_sync(0xffffffffu, d[i], o);
                    }
                    if (lane == 0) {
                        const int l0 = wrow + g * GR;
                        d_s[half][l0] = d[0];
                        if (cnt > 1) d_s[half][l0 + 1] = d[1];
                        if (cnt > 2) d_s[half][l0 + 2] = d[2];
                        if (cnt > 3) d_s[half][l0 + 3] = d[3];
                    }
                }
            }
            __syncthreads();   // d_s ready; prev-pass stage/acc_s consumed

            // phase 2: accumulate column sums with u = 1/(d0+d1)
            float4 acc[4];
#pragma unroll
            for (int f = 0; f < 4; f++) acc[f] = make_float4(0.f, 0.f, 0.f, 0.f);

            for (int g = 0; g < HRW / GR; g++) {
                const int r0  = rg + g * GR;
                const int cnt = min(GR, nr - r0);
                if (cnt <= 0) break;                     // warp-uniform
#pragma unroll
                for (int i = 0; i < GR; i++) {
                    if (i >= cnt) break;
                    const int lr = wrow + g * GR + i;
                    const float u = FIRST ? 1.0f
                                          : 1.0f / (d_s[0][lr] + d_s[1][lr]);
                    const float4* rp = sb + (size_t)(r0 + i) * 256;
#pragma unroll
                    for (int f = 0; f < 4; f++)
                        if (128 * f < mylim) {
                            float4 x = rp[cbase + f * 32];
                            acc[f].x += (x.x + EPS) * u;
                            acc[f].y += (x.y + EPS) * u;
                            acc[f].z += (x.z + EPS) * u;
                            acc[f].w += (x.w + EPS) * u;
                        }
                }
            }

            // CTA-level reduction: 8 warps per column half
#pragma unroll
            for (int f = 0; f < 4; f++) stage[warp][f * 32 + lane] = acc[f];
            __syncthreads();
            if (threadIdx.x < 256) {
                const int q = threadIdx.x;       // col-quad 0..255
                const int h = q >> 7;
                const int idx = q & 127;
                float4 t = stage[h * 8][idx];
#pragma unroll
                for (int k = 1; k < 8; k++) {
                    float4 a = stage[h * 8 + k][idx];
                    t.x += a.x; t.y += a.y; t.z += a.z; t.w += a.w;
                }
                ((float4*)acc_s)[q] = t;
            }

            // Cross-CTA column reduction + v update (rank owns 128 cols)
            CLUSTER_SYNC();
            if (threadIdx.x < RPC) {
                const int col = rank * RPC + threadIdx.x;
                float sum = 0.0f;
#pragma unroll
                for (int r = 0; r < CSZ; r++)
                    sum += ld_cluster(mapa_u32(a_acc + 4u * col, r));
                const float vn = (col < nc) ? (1.0f / sum) : 0.0f;
#pragma unroll
                for (int r = 0; r < CSZ; r++)
                    st_cluster(mapa_u32(a_v + 4u * col, r), vn);
            }
            CLUSTER_SYNC();
            __syncthreads();   // stage/acc_s reuse next pass
        }

        // ---- final pass: u9 = 1/(M v8), write out = (s+eps)*u9*v8
        {
            float4 v4[4];
            const float4* vv = (const float4*)v_s;
#pragma unroll
            for (int f = 0; f < 4; f++)
                v4[f] = (128 * f < mylim) ? vv[cbase + f * 32]
                                          : make_float4(0.f, 0.f, 0.f, 0.f);

            // phase 1: dots for u9
            for (int g = 0; g < HRW / GR; g++) {
                const int r0  = rg + g * GR;
                const int cnt = min(GR, nr - r0);
                if (cnt <= 0) break;
                float4 dv[GR];
#pragma unroll
                for (int i = 0; i < GR; i++)
                    dv[i] = make_float4(0.f, 0.f, 0.f, 0.f);
#pragma unroll
                for (int i = 0; i < GR; i++) {
                    if (i >= cnt) break;
                    const float4* rp = sb + (size_t)(r0 + i) * 256;
#pragma unroll
                    for (int f = 0; f < 4; f++)
                        if (128 * f < mylim) {
                            float4 x = rp[cbase + f * 32];
                            dv[i].x += (x.x + EPS) * v4[f].x;
                            dv[i].y += (x.y + EPS) * v4[f].y;
                            dv[i].z += (x.z + EPS) * v4[f].z;
                            dv[i].w += (x.w + EPS) * v4[f].w;
                        }
                }
                float d[GR];
#pragma unroll
                for (int i = 0; i < GR; i++)
                    d[i] = (dv[i].x + dv[i].y) + (dv[i].z + dv[i].w);
#pragma unroll
                for (int o = 16; o; o >>= 1) {
#pragma unroll
                    for (int i = 0; i < GR; i++)
                        d[i] += __shfl_xor_sync(0xffffffffu, d[i], o);
                }
                if (lane == 0) {
                    const int l0 = wrow + g * GR;
                    d_s[half][l0] = d[0];
                    if (cnt > 1) d_s[half][l0 + 1] = d[1];
                    if (cnt > 2) d_s[half][l0 + 2] = d[2];
                    if (cnt > 3) d_s[half][l0 + 3] = d[3];
                }
            }
            __syncthreads();

            // phase 2: write
            float4* ob = (float4*)(out + (size_t)b * NN * NN);
            const float4 z4 = make_float4(0.f, 0.f, 0.f, 0.f);
            for (int g = 0; g < HRW / GR; g++) {
                const int r0 = rg + g * GR;
#pragma unroll
                for (int i = 0; i < GR; i++) {
                    const int gr = r0 + i;
                    const int lr = wrow + g * GR + i;
                    float4* op = ob + (size_t)gr * 256;
                    if (gr >= nr) {                      // invalid row: zeros
#pragma unroll
                        for (int f = 0; f < 4; f++)
                            __stcs(&op[cbase + f * 32], z4);
                        continue;
                    }
                    const float u = 1.0f / (d_s[0][lr] + d_s[1][lr]);
                    const float4* rp = sb + (size_t)gr * 256;
#pragma unroll
                    for (int f = 0; f < 4; f++) {
                        if (128 * f < mylim) {
                            float4 x = rp[cbase + f * 32];
                            float4 o;
                            o.x = (x.x + EPS) * u * v4[f].x;
                            o.y = (x.y + EPS) * u * v4[f].y;
                            o.z = (x.z + EPS) * u * v4[f].z;
                            o.w = (x.w + EPS) * u * v4[f].w;
                            __stcs(&op[cbase + f * 32], o);  // v==0 past nc -> 0
                        } else {
                            __stcs(&op[cbase + f * 32], z4);
                        }
                    }
                }
            }
            __syncthreads();   // d_s reuse next batch
        }
        // Next batch's first post-write cluster barrier orders peer v_s/acc_s
        // writes after every rank finished reading them (symmetric arrive).
    }
}

extern "C" void kernel_launch(void* const* d_in, const int* in_sizes, int n_in,
                              void* d_out, int out_size)
{
    const float* s = (const float*)d_in[0];
    const int *nrows, *ncols;
    if (n_in >= 5) {          // order: s, n1, n2, nrows, ncols
        nrows = (const int*)d_in[3];
        ncols = (const int*)d_in[4];
    } else {                  // fallback: s, nrows, ncols
        nrows = (const int*)d_in[1];
        ncols = (const int*)d_in[2];
    }
    float* out = (float*)d_out;

    sinkhorn_kernel<<<dim3(CSZ, NCLUS), 512>>>(s, out, nrows, ncols);
}